// round 6
// baseline (speedup 1.0000x reference)
#include <cuda_runtime.h>
#include <mma.h>
#include <cuda_fp16.h>
#include <cstdint>

#define BB 256
#define TT 2048
#define HH 64

using namespace nvcuda;

// ---------- scratch ----------
__device__ __half g_out1h[(size_t)BB * TT * 128];  // layer-1 output fp16 [B,T,128] (fwd|bwd)
__device__ __half g_B1[2][256 * 144];              // l1 fused B (hi/lo split), col-major ld=144
__device__ __half g_B2[256 * 256];                 // l2 fused B (hi/lo recurrent), col-major ld=256

// ---------- activations ----------
__device__ __forceinline__ float tanh_f(float x) {
    float y; asm("tanh.approx.f32 %0, %1;" : "=f"(y) : "f"(x)); return y;
}
__device__ __forceinline__ float sigmoid_f(float x) {
    return fmaf(tanh_f(0.5f * x), 0.5f, 0.5f);
}

// gate-permuted column mapping: col n -> weight row (gate-major i,f,g,o)
__device__ __forceinline__ int perm_row(int n) {
    int T = n >> 4, c = n & 15;
    int j = T * 4 + ((c & 7) >> 1);
    int gam = (c < 8) ? (c & 1) : 2 + (c & 1);
    return gam * 64 + j;
}

__device__ __forceinline__ __half hi_h(float v) { return __float2half_rn(v); }
__device__ __forceinline__ __half lo_h(float v) {
    return __float2half_rn(v - __half2float(__float2half_rn(v)));
}

// =====================================================================
// Build fused B matrices. Block n = output column (gate-permuted).
// B1 rows: [Whh_hi(64) | Whh_lo(64) | Wih_hi(4) | Wih_lo(4) | 0-pad(8)]
// B2 rows: [Whh2_hi(64) | Whh2_lo(64) | Wih2 fp16(128)]
// =====================================================================
__global__ void build_B(const float* __restrict__ Wih_f, const float* __restrict__ Whh_f,
                        const float* __restrict__ Wih_b, const float* __restrict__ Whh_b,
                        const float* __restrict__ Wih2,  const float* __restrict__ Whh2)
{
    const int n = blockIdx.x;
    const int k = threadIdx.x;
    const int r = perm_row(n);

    if (k < 144) {
        __half vf, vb;
        if      (k < 64)  { vf = hi_h(Whh_f[r * 64 + k]);          vb = hi_h(Whh_b[r * 64 + k]); }
        else if (k < 128) { vf = lo_h(Whh_f[r * 64 + (k - 64)]);   vb = lo_h(Whh_b[r * 64 + (k - 64)]); }
        else if (k < 132) { vf = hi_h(Wih_f[r * 4 + (k - 128)]);   vb = hi_h(Wih_b[r * 4 + (k - 128)]); }
        else if (k < 136) { vf = lo_h(Wih_f[r * 4 + (k - 132)]);   vb = lo_h(Wih_b[r * 4 + (k - 132)]); }
        else              { vf = __ushort_as_half(0);              vb = __ushort_as_half(0); }
        g_B1[0][n * 144 + k] = vf;
        g_B1[1][n * 144 + k] = vb;
    }
    if (k < 256) {
        __half v;
        if      (k < 64)  v = hi_h(Whh2[r * 64 + k]);
        else if (k < 128) v = lo_h(Whh2[r * 64 + (k - 64)]);
        else              v = __float2half_rn(Wih2[r * 128 + (k - 128)]);
        g_B2[n * 256 + k] = v;
    }
}

// =====================================================================
// Layer-1 TC scan: 8 samples/block, one direction, 64 blocks.
// A = [h_hi(64) | h_lo(64) | x_hi(4) | x_lo(4) | pad(8)] fp16, K=144.
// =====================================================================
__global__ __launch_bounds__(256, 1)
void l1_scan(const float* __restrict__ x,
             const float* __restrict__ b_f, const float* __restrict__ b_b)
{
    const int grp = blockIdx.x >> 1;
    const int dir = blockIdx.x & 1;
    const int s0  = grp * 8;
    const int tid = threadIdx.x, lane = tid & 31, w = tid >> 5;

    __shared__ __half A[2][16 * 144];

    for (int i = tid; i < 16 * 144; i += 256) { A[0][i] = __ushort_as_half(0); A[1][i] = __ushort_as_half(0); }

    // register-resident B fragments: warp w owns n-tiles 2w, 2w+1
    wmma::fragment<wmma::matrix_b, 16, 16, 16, __half, wmma::col_major> bf[2][9];
    {
        const __half* B = g_B1[dir];
#pragma unroll
        for (int Ti = 0; Ti < 2; Ti++) {
            const int n0 = (2 * w + Ti) * 16;
#pragma unroll
            for (int k = 0; k < 9; k++)
                wmma::load_matrix_sync(bf[Ti][k], B + (size_t)n0 * 144 + k * 16, 144);
        }
    }

    const int step = dir ? -1 : 1;
    const int t0   = dir ? TT - 1 : 0;

    // epilogue identity
    const int es = lane >> 2;
    const int p  = lane & 3;
    const int jA = 8 * w + p;
    const int jB = 8 * w + 4 + p;
    const float* bv = dir ? b_b : b_f;
    const float biA = bv[jA],       bfA = bv[64 + jA];
    const float bgA = bv[128 + jA], boA = bv[192 + jA];
    const float biB = bv[jB],       bfB = bv[64 + jB];
    const float bgB = bv[128 + jB], boB = bv[192 + jB];
    float cA = 0.f, cB = 0.f;

    // x feeder: warp 0 lanes: sample xs, component xj
    const bool xl = (w == 0);
    const int xs = lane >> 2, xj = lane & 3;
    const float* xp = x + ((size_t)(s0 + xs) * TT + t0) * 4 + xj;
    float xv1 = 0.f;
    if (xl) {
        float x0 = __ldg(xp);
        A[0][xs * 144 + 128 + xj] = hi_h(x0);
        A[0][xs * 144 + 132 + xj] = lo_h(x0);
        xv1 = __ldg(xp + step * 4);
    }
    __syncthreads();

    __half* outA = g_out1h + ((size_t)(s0 + es) * TT + t0) * 128 + dir * 64 + jA;
    __half* outB = outA + 4;

    for (int t = 0; t < TT; t++) {
        const int cur = t & 1, nxt = cur ^ 1;

        wmma::fragment<wmma::accumulator, 16, 16, 16, float> acc[2], ac2[2];
        wmma::fill_fragment(acc[0], 0.f); wmma::fill_fragment(acc[1], 0.f);
        wmma::fill_fragment(ac2[0], 0.f); wmma::fill_fragment(ac2[1], 0.f);
        {
            wmma::fragment<wmma::matrix_a, 16, 16, 16, __half, wmma::row_major> af;
#pragma unroll
            for (int k = 0; k < 9; k++) {
                wmma::load_matrix_sync(af, &A[cur][k * 16], 144);
                if (k & 1) { wmma::mma_sync(ac2[0], af, bf[0][k], ac2[0]); wmma::mma_sync(ac2[1], af, bf[1][k], ac2[1]); }
                else       { wmma::mma_sync(acc[0], af, bf[0][k], acc[0]); wmma::mma_sync(acc[1], af, bf[1][k], acc[1]); }
            }
        }

        float xv2 = 0.f;
        if (xl && t + 2 < TT) xv2 = __ldg(xp + (t + 2) * step * 4);

        {
            float i0 = sigmoid_f(acc[0].x[0] + ac2[0].x[0] + biA);
            float f0 = sigmoid_f(acc[0].x[1] + ac2[0].x[1] + bfA);
            float g0 = tanh_f   (acc[0].x[4] + ac2[0].x[4] + bgA);
            float o0 = sigmoid_f(acc[0].x[5] + ac2[0].x[5] + boA);
            cA = f0 * cA + i0 * g0;
            float hA = o0 * tanh_f(cA);

            float i1 = sigmoid_f(acc[1].x[0] + ac2[1].x[0] + biB);
            float f1 = sigmoid_f(acc[1].x[1] + ac2[1].x[1] + bfB);
            float g1 = tanh_f   (acc[1].x[4] + ac2[1].x[4] + bgB);
            float o1 = sigmoid_f(acc[1].x[5] + ac2[1].x[5] + boB);
            cB = f1 * cB + i1 * g1;
            float hB = o1 * tanh_f(cB);

            __half hAhi = hi_h(hA), hBhi = hi_h(hB);
            A[nxt][es * 144 + jA]      = hAhi;
            A[nxt][es * 144 + 64 + jA] = lo_h(hA);
            A[nxt][es * 144 + jB]      = hBhi;
            A[nxt][es * 144 + 64 + jB] = lo_h(hB);
            *outA = hAhi; *outB = hBhi;
            outA += step * 128; outB += step * 128;
        }

        if (xl) {
            A[nxt][xs * 144 + 128 + xj] = hi_h(xv1);
            A[nxt][xs * 144 + 132 + xj] = lo_h(xv1);
        }
        xv1 = xv2;

        __syncthreads();
    }
}

// =====================================================================
// Layer-2 TC scan (input GEMM fused): 8 samples/block, 32 blocks.
// A = [h_hi(64) | h_lo(64) | out1_t(128)] fp16, K=256. Fused FC.
// =====================================================================
__global__ __launch_bounds__(256, 1)
void l2_scan(const float* __restrict__ b2,
             const float* __restrict__ Wfc, const float* __restrict__ bfc,
             float* __restrict__ out)
{
    const int s0  = blockIdx.x * 8;
    const int tid = threadIdx.x, lane = tid & 31, w = tid >> 5;

    __shared__ __half A[2][16 * 256];
    __shared__ float  sred[8][64];
    __shared__ float  wfc[64];

    for (int i = tid; i < 16 * 256; i += 256) { A[0][i] = __ushort_as_half(0); A[1][i] = __ushort_as_half(0); }
    if (tid < 64) wfc[tid] = __ldg(Wfc + tid);

    wmma::fragment<wmma::matrix_b, 16, 16, 16, __half, wmma::col_major> bf[2][16];
#pragma unroll
    for (int Ti = 0; Ti < 2; Ti++) {
        const int n0 = (2 * w + Ti) * 16;
#pragma unroll
        for (int k = 0; k < 16; k++)
            wmma::load_matrix_sync(bf[Ti][k], g_B2 + (size_t)n0 * 256 + k * 16, 256);
    }

    const int es = lane >> 2;
    const int p  = lane & 3;
    const int jA = 8 * w + p;
    const int jB = 8 * w + 4 + p;
    const float biA = b2[jA],       bfA = b2[64 + jA];
    const float bgA = b2[128 + jA], boA = b2[192 + jA];
    const float biB = b2[jB],       bfB = b2[64 + jB];
    const float bgB = b2[128 + jB], boB = b2[192 + jB];
    float cA = 0.f, cB = 0.f;
    float hA = 0.f, hB = 0.f;

    // out1 feeder: threads 0..127: sample fs, 8-half chunk fc
    const bool fl = (tid < 128);
    const int fs = tid >> 4, fc = tid & 15;
    const uint4* fp = (const uint4*)(g_out1h + ((size_t)(s0 + fs) * TT) * 128) + fc;
    uint4 on = make_uint4(0, 0, 0, 0);
    if (fl) {
        uint4 oc = __ldg(fp);
        *(uint4*)&A[0][fs * 256 + 128 + fc * 8] = oc;
        on = __ldg(fp + 16);
    }
    __syncthreads();

    for (int t = 0; t < TT; t++) {
        const int cur = t & 1, nxt = cur ^ 1;

        wmma::fragment<wmma::accumulator, 16, 16, 16, float> acc[2], ac2[2];
        wmma::fill_fragment(acc[0], 0.f); wmma::fill_fragment(acc[1], 0.f);
        wmma::fill_fragment(ac2[0], 0.f); wmma::fill_fragment(ac2[1], 0.f);
        {
            wmma::fragment<wmma::matrix_a, 16, 16, 16, __half, wmma::row_major> af;
#pragma unroll
            for (int k = 0; k < 16; k++) {
                wmma::load_matrix_sync(af, &A[cur][k * 16], 256);
                if (k & 1) { wmma::mma_sync(ac2[0], af, bf[0][k], ac2[0]); wmma::mma_sync(ac2[1], af, bf[1][k], ac2[1]); }
                else       { wmma::mma_sync(acc[0], af, bf[0][k], acc[0]); wmma::mma_sync(acc[1], af, bf[1][k], acc[1]); }
            }
        }

        uint4 o2 = make_uint4(0, 0, 0, 0);
        if (fl && t + 2 < TT) o2 = __ldg(fp + (size_t)(t + 2) * 16);

        {
            float i0 = sigmoid_f(acc[0].x[0] + ac2[0].x[0] + biA);
            float f0 = sigmoid_f(acc[0].x[1] + ac2[0].x[1] + bfA);
            float g0 = tanh_f   (acc[0].x[4] + ac2[0].x[4] + bgA);
            float o0 = sigmoid_f(acc[0].x[5] + ac2[0].x[5] + boA);
            cA = f0 * cA + i0 * g0;
            hA = o0 * tanh_f(cA);

            float i1 = sigmoid_f(acc[1].x[0] + ac2[1].x[0] + biB);
            float f1 = sigmoid_f(acc[1].x[1] + ac2[1].x[1] + bfB);
            float g1 = tanh_f   (acc[1].x[4] + ac2[1].x[4] + bgB);
            float o1 = sigmoid_f(acc[1].x[5] + ac2[1].x[5] + boB);
            cB = f1 * cB + i1 * g1;
            hB = o1 * tanh_f(cB);

            A[nxt][es * 256 + jA]      = hi_h(hA);
            A[nxt][es * 256 + 64 + jA] = lo_h(hA);
            A[nxt][es * 256 + jB]      = hi_h(hB);
            A[nxt][es * 256 + 64 + jB] = lo_h(hB);
        }

        if (fl) *(uint4*)&A[nxt][fs * 256 + 128 + fc * 8] = on;
        on = o2;

        __syncthreads();
    }

    // fused FC (fp32 h straight from registers)
    sred[es][jA] = hA * wfc[jA];
    sred[es][jB] = hB * wfc[jB];
    __syncthreads();
    if (tid < 8) {
        float acc = __ldg(bfc);
#pragma unroll
        for (int k = 0; k < 64; k++) acc += sred[tid][k];
        out[s0 + tid] = acc;
    }
}

// =====================================================================
extern "C" void kernel_launch(void* const* d_in, const int* in_sizes, int n_in,
                              void* d_out, int out_size)
{
    const float* x     = (const float*)d_in[0];
    const float* Wih_f = (const float*)d_in[1];
    const float* Whh_f = (const float*)d_in[2];
    const float* b_f   = (const float*)d_in[3];
    const float* Wih_b = (const float*)d_in[4];
    const float* Whh_b = (const float*)d_in[5];
    const float* b_b   = (const float*)d_in[6];
    const float* Wih2  = (const float*)d_in[7];
    const float* Whh2  = (const float*)d_in[8];
    const float* b2    = (const float*)d_in[9];
    const float* Wfc   = (const float*)d_in[10];
    const float* bfc   = (const float*)d_in[11];
    float* out = (float*)d_out;

    build_B<<<256, 256>>>(Wih_f, Whh_f, Wih_b, Whh_b, Wih2, Whh2);
    l1_scan<<<64, 256>>>(x, b_f, b_b);
    l2_scan<<<32, 256>>>(b2, Wfc, bfc, out);
}

// round 7
// speedup vs baseline: 2.1017x; 2.1017x over previous
#include <cuda_runtime.h>
#include <cuda_fp16.h>
#include <cstdint>

#define BB 256
#define TT 2048

// ---------- scratch ----------
__device__ __half g_out1h[(size_t)BB * TT * 128];  // layer-1 output fp16 [B,T,128] (fwd|bwd)
__device__ __half g_B1[2][256 * 144];              // l1 fused B [n][k], gate-permuted n
__device__ __half g_B2[256 * 256];                 // l2 fused B [n][k]

// ---------- helpers ----------
__device__ __forceinline__ float tanh_f(float x) {
    float y; asm("tanh.approx.f32 %0, %1;" : "=f"(y) : "f"(x)); return y;
}
__device__ __forceinline__ float sigmoid_f(float x) {
    return fmaf(tanh_f(0.5f * x), 0.5f, 0.5f);
}
__device__ __forceinline__ __half hi_h(float v) { return __float2half_rn(v); }
__device__ __forceinline__ __half lo_h(float v) {
    return __float2half_rn(v - __half2float(__float2half_rn(v)));
}
__device__ __forceinline__ uint32_t smem_u32(const void* p) {
    uint32_t a;
    asm("{ .reg .u64 t; cvta.to.shared.u64 t, %1; cvt.u32.u64 %0, t; }" : "=r"(a) : "l"(p));
    return a;
}
__device__ __forceinline__ void ldsm4(uint32_t* r, uint32_t addr) {
    asm volatile("ldmatrix.sync.aligned.m8n8.x4.shared.b16 {%0,%1,%2,%3}, [%4];"
                 : "=r"(r[0]), "=r"(r[1]), "=r"(r[2]), "=r"(r[3]) : "r"(addr));
}
__device__ __forceinline__ void mma16816(float* d, const uint32_t* a, const uint32_t* b) {
    asm volatile("mma.sync.aligned.m16n8k16.row.col.f32.f16.f16.f32 "
                 "{%0,%1,%2,%3},{%4,%5,%6,%7},{%8,%9},{%0,%1,%2,%3};"
                 : "+f"(d[0]), "+f"(d[1]), "+f"(d[2]), "+f"(d[3])
                 : "r"(a[0]), "r"(a[1]), "r"(a[2]), "r"(a[3]), "r"(b[0]), "r"(b[1]));
}

// gate-permuted column map: global col n -> weight row (gate-major i,f,g,o)
// n8-tile = n>>3; warp w = tile>>2; u = (tile>>1)&1; odd = tile&1; c = n&7
// j = w*8 + u*4 + (c>>1); gate = 2*odd + (c&1); row = gate*64 + j
__device__ __forceinline__ int perm_row(int n) {
    int tile = n >> 3, c = n & 7;
    int w = tile >> 2, u = (tile >> 1) & 1, odd = tile & 1;
    int j = w * 8 + u * 4 + (c >> 1);
    int gate = 2 * odd + (c & 1);
    return gate * 64 + j;
}

// =====================================================================
// Build fused B. B1 k: [Whh_hi 0-63 | Whh_lo 64-127 | Wih_hi 128-131 |
// Wih_lo 132-135 | 0 136-143].  B2 k: [Whh2_hi | Whh2_lo | Wih2 fp16 128-255]
// =====================================================================
__global__ void build_B(const float* __restrict__ Wih_f, const float* __restrict__ Whh_f,
                        const float* __restrict__ Wih_b, const float* __restrict__ Whh_b,
                        const float* __restrict__ Wih2,  const float* __restrict__ Whh2)
{
    const int n = blockIdx.x;
    const int k = threadIdx.x;
    const int r = perm_row(n);

    if (k < 144) {
        __half vf, vb;
        if      (k < 64)  { vf = hi_h(Whh_f[r * 64 + k]);        vb = hi_h(Whh_b[r * 64 + k]); }
        else if (k < 128) { vf = lo_h(Whh_f[r * 64 + (k - 64)]); vb = lo_h(Whh_b[r * 64 + (k - 64)]); }
        else if (k < 132) { vf = hi_h(Wih_f[r * 4 + (k - 128)]); vb = hi_h(Wih_b[r * 4 + (k - 128)]); }
        else if (k < 136) { vf = lo_h(Wih_f[r * 4 + (k - 132)]); vb = lo_h(Wih_b[r * 4 + (k - 132)]); }
        else              { vf = __ushort_as_half(0);            vb = __ushort_as_half(0); }
        g_B1[0][n * 144 + k] = vf;
        g_B1[1][n * 144 + k] = vb;
    }
    {
        __half v;
        if      (k < 64)  v = hi_h(Whh2[r * 64 + k]);
        else if (k < 128) v = lo_h(Whh2[r * 64 + (k - 64)]);
        else              v = __float2half_rn(Wih2[r * 128 + (k - 128)]);
        g_B2[n * 256 + k] = v;
    }
}

// =====================================================================
// Layer-1 scan: 16 samples/block, one direction. 32 blocks, 256 threads.
// A[16 x 144] fp16 (stride 152), double buffered. K-tiles: 8 h + 1 x.
// =====================================================================
#define AS1 152
__global__ __launch_bounds__(256, 1)
void l1_scan(const float* __restrict__ x,
             const float* __restrict__ b_f, const float* __restrict__ b_b)
{
    const int grp = blockIdx.x >> 1;
    const int dir = blockIdx.x & 1;
    const int s0  = grp * 16;
    const int tid = threadIdx.x, lane = tid & 31, w = tid >> 5;

    __shared__ __half A[2 * 16 * AS1];

    for (int i = tid; i < 2 * 16 * AS1; i += 256) A[i] = __ushort_as_half(0);

    // B fragments: warp w owns n8-tiles 4w..4w+3 (tt = u*2+odd)
    uint32_t bf[4][9][2];
    {
        const __half* B = g_B1[dir];
#pragma unroll
        for (int tt = 0; tt < 4; tt++) {
            const int n = (w * 4 + tt) * 8 + (lane >> 2);
#pragma unroll
            for (int kt = 0; kt < 9; kt++) {
                const __half* p = B + (size_t)n * 144 + kt * 16 + 2 * (lane & 3);
                bf[tt][kt][0] = *(const uint32_t*)p;
                bf[tt][kt][1] = *(const uint32_t*)(p + 8);
            }
        }
    }

    // biases (fp32 epilogue)
    const float* bv = dir ? b_b : b_f;
    const int j0 = w * 8 + (lane & 3), j1 = j0 + 4;
    const float bi0 = bv[j0],       bff0 = bv[64 + j0], bg0 = bv[128 + j0], bo0 = bv[192 + j0];
    const float bi1 = bv[j1],       bff1 = bv[64 + j1], bg1 = bv[128 + j1], bo1 = bv[192 + j1];

    // ldmatrix lane addresses for both buffers
    const uint32_t lrow = lane & 15, lcol = (lane >> 4) * 8;
    const uint32_t aaddr0 = smem_u32(A) + (lrow * AS1 + lcol) * 2;
    const uint32_t aaddr1 = aaddr0 + 16 * AS1 * 2;

    const int step = dir ? -1 : 1;
    const int t0   = dir ? TT - 1 : 0;

    // x feeder: threads 0..63 (sample fsx, component comp)
    const bool xf = tid < 64;
    const int fsx = tid >> 2, comp = tid & 3;
    const float* xp = x + ((size_t)(s0 + fsx) * TT + t0) * 4 + comp;
    float vn = 0.f, vi = 0.f;
    if (xf) {
        float v0 = __ldg(xp);
        A[fsx * AS1 + 128 + comp] = hi_h(v0);
        A[fsx * AS1 + 132 + comp] = lo_h(v0);
        vn = __ldg(xp + step * 4);
        vi = __ldg(xp + 2 * step * 4);
    }
    __syncthreads();

    // output flush identity
    const int ffs = tid >> 4, ffc = tid & 15;
    __half* fout = g_out1h + (size_t)(s0 + ffs) * TT * 128 + dir * 64 + ffc * 4;

    const int srow0 = lane >> 2;
    float c[4] = {0.f, 0.f, 0.f, 0.f};

    for (int t = 0; t < TT; t++) {
        const int cur = t & 1, nxt = cur ^ 1;
        const uint32_t aaddr = cur ? aaddr1 : aaddr0;
        __half* An = A + nxt * 16 * AS1;

        float acc[4][4];
#pragma unroll
        for (int i = 0; i < 4; i++) { acc[i][0] = 0.f; acc[i][1] = 0.f; acc[i][2] = 0.f; acc[i][3] = 0.f; }
#pragma unroll
        for (int kt = 0; kt < 9; kt++) {
            uint32_t a[4];
            ldsm4(a, aaddr + kt * 32);
            mma16816(acc[0], a, bf[0][kt]);
            mma16816(acc[1], a, bf[1][kt]);
            mma16816(acc[2], a, bf[2][kt]);
            mma16816(acc[3], a, bf[3][kt]);
        }

        // flush previous step's h (coalesced, reads A[cur] h_hi region)
        if (t) {
            const __half* Ac = A + cur * 16 * AS1;
            uint2 v = *(const uint2*)(Ac + ffs * AS1 + ffc * 4);
            *(uint2*)(fout + (size_t)(t0 + (t - 1) * step) * 128) = v;
        }

        // x feeder for t+1
        if (xf) {
            An[fsx * AS1 + 128 + comp] = hi_h(vn);
            An[fsx * AS1 + 132 + comp] = lo_h(vn);
            vn = vi;
            vi = (t + 3 < TT) ? __ldg(xp + (size_t)(t + 3) * step * 4) : 0.f;
        }

        // register epilogue: items (u, rh)
#pragma unroll
        for (int u = 0; u < 2; u++) {
#pragma unroll
            for (int rh = 0; rh < 2; rh++) {
                const int m = u * 2 + rh;
                const float bi = u ? bi1 : bi0, bff = u ? bff1 : bff0;
                const float bg = u ? bg1 : bg0, bo = u ? bo1 : bo0;
                float iv = sigmoid_f(acc[u * 2][rh * 2]     + bi);
                float fv = sigmoid_f(acc[u * 2][rh * 2 + 1] + bff);
                float gv = tanh_f   (acc[u * 2 + 1][rh * 2]     + bg);
                float ov = sigmoid_f(acc[u * 2 + 1][rh * 2 + 1] + bo);
                c[m] = fv * c[m] + iv * gv;
                float hh = ov * tanh_f(c[m]);
                const int srow = srow0 + rh * 8;
                const int jc = u ? j1 : j0;
                An[srow * AS1 + jc]      = hi_h(hh);
                An[srow * AS1 + 64 + jc] = lo_h(hh);
            }
        }
        __syncthreads();
    }

    // final flush (h of step TT-1 lives in A[0])
    {
        uint2 v = *(const uint2*)(A + ffs * AS1 + ffc * 4);
        *(uint2*)(fout + (size_t)(t0 + (TT - 1) * step) * 128) = v;
    }
}

// =====================================================================
// Layer-2 scan (input GEMM fused): 16 samples/block, 16 blocks.
// A[16 x 256] fp16 (stride 264): [h_hi | h_lo | out1 128]. 16 k-tiles.
// =====================================================================
#define AS2 264
__global__ __launch_bounds__(256, 1)
void l2_scan(const float* __restrict__ b2,
             const float* __restrict__ Wfc, const float* __restrict__ bfc,
             float* __restrict__ out)
{
    const int s0  = blockIdx.x * 16;
    const int tid = threadIdx.x, lane = tid & 31, w = tid >> 5;

    __shared__ __half A[2 * 16 * AS2];
    __shared__ float  sred[16 * 64];

    for (int i = tid; i < 2 * 16 * AS2; i += 256) A[i] = __ushort_as_half(0);

    uint32_t bf[4][16][2];
#pragma unroll
    for (int tt = 0; tt < 4; tt++) {
        const int n = (w * 4 + tt) * 8 + (lane >> 2);
#pragma unroll
        for (int kt = 0; kt < 16; kt++) {
            const __half* p = g_B2 + (size_t)n * 256 + kt * 16 + 2 * (lane & 3);
            bf[tt][kt][0] = *(const uint32_t*)p;
            bf[tt][kt][1] = *(const uint32_t*)(p + 8);
        }
    }

    const int j0 = w * 8 + (lane & 3), j1 = j0 + 4;
    const float bi0 = b2[j0], bff0 = b2[64 + j0], bg0 = b2[128 + j0], bo0 = b2[192 + j0];
    const float bi1 = b2[j1], bff1 = b2[64 + j1], bg1 = b2[128 + j1], bo1 = b2[192 + j1];
    const float wf0 = __ldg(Wfc + j0), wf1 = __ldg(Wfc + j1);

    const uint32_t lrow = lane & 15, lcol = (lane >> 4) * 8;
    const uint32_t aaddr0 = smem_u32(A) + (lrow * AS2 + lcol) * 2;
    const uint32_t aaddr1 = aaddr0 + 16 * AS2 * 2;

    // out1 feeder: all 256 threads (sample ffs, 16B chunk ffc)
    const int ffs = tid >> 4, ffc = tid & 15;
    const uint4* fp = (const uint4*)(g_out1h + (size_t)(s0 + ffs) * TT * 128) + ffc;
    uint4 vn, vi;
    {
        uint4 v0 = __ldg(fp);
        *(uint4*)(A + ffs * AS2 + 128 + ffc * 8) = v0;
        vn = __ldg(fp + 16);
        vi = __ldg(fp + 32);
    }
    __syncthreads();

    const int srow0 = lane >> 2;
    float c[4] = {0.f, 0.f, 0.f, 0.f};
    float h[4] = {0.f, 0.f, 0.f, 0.f};

    for (int t = 0; t < TT; t++) {
        const int cur = t & 1, nxt = cur ^ 1;
        const uint32_t aaddr = cur ? aaddr1 : aaddr0;
        __half* An = A + nxt * 16 * AS2;

        float acc[4][4];
#pragma unroll
        for (int i = 0; i < 4; i++) { acc[i][0] = 0.f; acc[i][1] = 0.f; acc[i][2] = 0.f; acc[i][3] = 0.f; }
#pragma unroll
        for (int kt = 0; kt < 16; kt++) {
            uint32_t a[4];
            ldsm4(a, aaddr + kt * 32);
            mma16816(acc[0], a, bf[0][kt]);
            mma16816(acc[1], a, bf[1][kt]);
            mma16816(acc[2], a, bf[2][kt]);
            mma16816(acc[3], a, bf[3][kt]);
        }

        // feeder for t+1
        *(uint4*)(An + ffs * AS2 + 128 + ffc * 8) = vn;
        vn = vi;
        if (t + 3 < TT) vi = __ldg(fp + (size_t)(t + 3) * 16);

#pragma unroll
        for (int u = 0; u < 2; u++) {
#pragma unroll
            for (int rh = 0; rh < 2; rh++) {
                const int m = u * 2 + rh;
                const float bi = u ? bi1 : bi0, bff = u ? bff1 : bff0;
                const float bg = u ? bg1 : bg0, bo = u ? bo1 : bo0;
                float iv = sigmoid_f(acc[u * 2][rh * 2]     + bi);
                float fv = sigmoid_f(acc[u * 2][rh * 2 + 1] + bff);
                float gv = tanh_f   (acc[u * 2 + 1][rh * 2]     + bg);
                float ov = sigmoid_f(acc[u * 2 + 1][rh * 2 + 1] + bo);
                c[m] = fv * c[m] + iv * gv;
                h[m] = ov * tanh_f(c[m]);
                const int srow = srow0 + rh * 8;
                const int jc = u ? j1 : j0;
                An[srow * AS2 + jc]      = hi_h(h[m]);
                An[srow * AS2 + 64 + jc] = lo_h(h[m]);
            }
        }
        __syncthreads();
    }

    // fused FC on final h
#pragma unroll
    for (int u = 0; u < 2; u++)
#pragma unroll
        for (int rh = 0; rh < 2; rh++) {
            const int m = u * 2 + rh;
            sred[(srow0 + rh * 8) * 64 + (u ? j1 : j0)] = h[m] * (u ? wf1 : wf0);
        }
    __syncthreads();
    if (tid < 16) {
        float acc = __ldg(bfc);
#pragma unroll
        for (int k = 0; k < 64; k++) acc += sred[tid * 64 + k];
        out[s0 + tid] = acc;
    }
}

// =====================================================================
extern "C" void kernel_launch(void* const* d_in, const int* in_sizes, int n_in,
                              void* d_out, int out_size)
{
    const float* x     = (const float*)d_in[0];
    const float* Wih_f = (const float*)d_in[1];
    const float* Whh_f = (const float*)d_in[2];
    const float* b_f   = (const float*)d_in[3];
    const float* Wih_b = (const float*)d_in[4];
    const float* Whh_b = (const float*)d_in[5];
    const float* b_b   = (const float*)d_in[6];
    const float* Wih2  = (const float*)d_in[7];
    const float* Whh2  = (const float*)d_in[8];
    const float* b2    = (const float*)d_in[9];
    const float* Wfc   = (const float*)d_in[10];
    const float* bfc   = (const float*)d_in[11];
    float* out = (float*)d_out;

    build_B<<<256, 256>>>(Wih_f, Whh_f, Wih_b, Whh_b, Wih2, Whh2);
    l1_scan<<<32, 256>>>(x, b_f, b_b);
    l2_scan<<<16, 256>>>(b2, Wfc, bfc, out);
}

// round 8
// speedup vs baseline: 2.1619x; 1.0286x over previous
#include <cuda_runtime.h>
#include <cuda_fp16.h>
#include <cstdint>

#define BB 256
#define TT 2048

// ---------- scratch ----------
__device__ __half g_out1h[(size_t)BB * TT * 128];     // layer-1 output fp16 [B,T,128] (fwd|bwd)
__device__ float  g_pre2p[(size_t)BB * TT * 256];     // l2 input preact, permuted [s][t][j*4+gate], bias folded
__device__ __half g_B1[2][256 * 144];                 // l1 fused B [n][k], gate-permuted n
__device__ __half g_B2s[256 * 128];                   // l2 scan B: [Whh2_hi|Whh2_lo], gate-permuted n
__device__ __half g_B2i[256 * 128];                   // pre2 GEMM B: Wih2 fp16, col n2=j*4+gate

// ---------- helpers ----------
__device__ __forceinline__ float tanh_f(float x) {
    float y; asm("tanh.approx.f32 %0, %1;" : "=f"(y) : "f"(x)); return y;
}
__device__ __forceinline__ float sigmoid_f(float x) {
    return fmaf(tanh_f(0.5f * x), 0.5f, 0.5f);
}
__device__ __forceinline__ __half hi_h(float v) { return __float2half_rn(v); }
__device__ __forceinline__ __half lo_h(float v) {
    return __float2half_rn(v - __half2float(__float2half_rn(v)));
}
__device__ __forceinline__ uint32_t smem_u32(const void* p) {
    uint32_t a;
    asm("{ .reg .u64 t; cvta.to.shared.u64 t, %1; cvt.u32.u64 %0, t; }" : "=r"(a) : "l"(p));
    return a;
}
__device__ __forceinline__ void ldsm4(uint32_t* r, uint32_t addr) {
    asm volatile("ldmatrix.sync.aligned.m8n8.x4.shared.b16 {%0,%1,%2,%3}, [%4];"
                 : "=r"(r[0]), "=r"(r[1]), "=r"(r[2]), "=r"(r[3]) : "r"(addr));
}
__device__ __forceinline__ void mma16816(float* d, const uint32_t* a, const uint32_t* b) {
    asm volatile("mma.sync.aligned.m16n8k16.row.col.f32.f16.f16.f32 "
                 "{%0,%1,%2,%3},{%4,%5,%6,%7},{%8,%9},{%0,%1,%2,%3};"
                 : "+f"(d[0]), "+f"(d[1]), "+f"(d[2]), "+f"(d[3])
                 : "r"(a[0]), "r"(a[1]), "r"(a[2]), "r"(a[3]), "r"(b[0]), "r"(b[1]));
}

// scan gate-permuted column map: col n -> weight row (gate-major i,f,g,o)
__device__ __forceinline__ int perm_row(int n) {
    int tile = n >> 3, c = n & 7;
    int w = tile >> 2, u = (tile >> 1) & 1, odd = tile & 1;
    int j = w * 8 + u * 4 + (c >> 1);
    int gate = 2 * odd + (c & 1);
    return gate * 64 + j;
}

// =====================================================================
// Build fused B matrices.
// =====================================================================
__global__ void build_B(const float* __restrict__ Wih_f, const float* __restrict__ Whh_f,
                        const float* __restrict__ Wih_b, const float* __restrict__ Whh_b,
                        const float* __restrict__ Wih2,  const float* __restrict__ Whh2)
{
    const int n = blockIdx.x;
    const int k = threadIdx.x;
    const int r = perm_row(n);

    if (k < 144) {
        __half vf, vb;
        if      (k < 64)  { vf = hi_h(Whh_f[r * 64 + k]);        vb = hi_h(Whh_b[r * 64 + k]); }
        else if (k < 128) { vf = lo_h(Whh_f[r * 64 + (k - 64)]); vb = lo_h(Whh_b[r * 64 + (k - 64)]); }
        else if (k < 132) { vf = hi_h(Wih_f[r * 4 + (k - 128)]); vb = hi_h(Wih_b[r * 4 + (k - 128)]); }
        else if (k < 136) { vf = lo_h(Wih_f[r * 4 + (k - 132)]); vb = lo_h(Wih_b[r * 4 + (k - 132)]); }
        else              { vf = __ushort_as_half(0);            vb = __ushort_as_half(0); }
        g_B1[0][n * 144 + k] = vf;
        g_B1[1][n * 144 + k] = vb;
    }
    if (k < 128) {
        // scan B (h recurrent, hi/lo)
        __half v = (k < 64) ? hi_h(Whh2[r * 64 + k]) : lo_h(Whh2[r * 64 + (k - 64)]);
        g_B2s[n * 128 + k] = v;
        // input-GEMM B: col n2 = j*4+gate -> weight row r2 = gate*64 + j
        const int r2 = (n & 3) * 64 + (n >> 2);
        g_B2i[n * 128 + k] = __float2half_rn(Wih2[r2 * 128 + k]);
    }
}

// =====================================================================
// Layer-1 scan: 8 samples/block, one direction. 64 blocks, 256 threads.
// A[16 x 144] fp16 (stride 152, rows 8-15 zero), double buffered.
// =====================================================================
#define AS1 152
__global__ __launch_bounds__(256, 1)
void l1_scan(const float* __restrict__ x,
             const float* __restrict__ b_f, const float* __restrict__ b_b)
{
    const int grp = blockIdx.x >> 1;
    const int dir = blockIdx.x & 1;
    const int s0  = grp * 8;
    const int tid = threadIdx.x, lane = tid & 31, w = tid >> 5;

    __shared__ __half A[2 * 16 * AS1];

    for (int i = tid; i < 2 * 16 * AS1; i += 256) A[i] = __ushort_as_half(0);

    uint32_t bf[4][9][2];
    {
        const __half* B = g_B1[dir];
#pragma unroll
        for (int tt = 0; tt < 4; tt++) {
            const int n = (w * 4 + tt) * 8 + (lane >> 2);
#pragma unroll
            for (int kt = 0; kt < 9; kt++) {
                const __half* p = B + (size_t)n * 144 + kt * 16 + 2 * (lane & 3);
                bf[tt][kt][0] = *(const uint32_t*)p;
                bf[tt][kt][1] = *(const uint32_t*)(p + 8);
            }
        }
    }

    const float* bv = dir ? b_b : b_f;
    const int j0 = w * 8 + (lane & 3), j1 = j0 + 4;
    const float bi0 = bv[j0], bff0 = bv[64 + j0], bg0 = bv[128 + j0], bo0 = bv[192 + j0];
    const float bi1 = bv[j1], bff1 = bv[64 + j1], bg1 = bv[128 + j1], bo1 = bv[192 + j1];

    const uint32_t lrow = lane & 15, lcol = (lane >> 4) * 8;
    const uint32_t aaddr0 = smem_u32(A) + (lrow * AS1 + lcol) * 2;
    const uint32_t aaddr1 = aaddr0 + 16 * AS1 * 2;

    const int step = dir ? -1 : 1;
    const int t0   = dir ? TT - 1 : 0;

    // x feeder: threads 0..31 (sample fsx, component comp)
    const bool xf = tid < 32;
    const int fsx = tid >> 2, comp = tid & 3;
    const float* xp = x + ((size_t)(s0 + fsx) * TT + t0) * 4 + comp;
    float vn = 0.f, vi = 0.f;
    if (xf) {
        float v0 = __ldg(xp);
        A[fsx * AS1 + 128 + comp] = hi_h(v0);
        A[fsx * AS1 + 132 + comp] = lo_h(v0);
        vn = __ldg(xp + step * 4);
        vi = __ldg(xp + 2 * step * 4);
    }
    __syncthreads();

    // output flush identity (threads 0..127: 8 samples x 16 chunks)
    const int ffs = tid >> 4, ffc = tid & 15;
    __half* fout = g_out1h + (size_t)(s0 + ffs) * TT * 128 + dir * 64 + ffc * 4;

    const int srow = lane >> 2;
    float c0 = 0.f, c1 = 0.f;

    for (int t = 0; t < TT; t++) {
        const int cur = t & 1, nxt = cur ^ 1;
        const uint32_t aaddr = cur ? aaddr1 : aaddr0;
        __half* An = A + nxt * 16 * AS1;

        float acc[4][4];
#pragma unroll
        for (int i = 0; i < 4; i++) { acc[i][0] = 0.f; acc[i][1] = 0.f; acc[i][2] = 0.f; acc[i][3] = 0.f; }
#pragma unroll
        for (int kt = 0; kt < 9; kt++) {
            uint32_t a[4];
            ldsm4(a, aaddr + kt * 32);
            mma16816(acc[0], a, bf[0][kt]);
            mma16816(acc[1], a, bf[1][kt]);
            mma16816(acc[2], a, bf[2][kt]);
            mma16816(acc[3], a, bf[3][kt]);
        }

        if (t && tid < 128) {
            const __half* Ac = A + cur * 16 * AS1;
            uint2 v = *(const uint2*)(Ac + ffs * AS1 + ffc * 4);
            *(uint2*)(fout + (size_t)(t0 + (t - 1) * step) * 128) = v;
        }

        if (xf) {
            An[fsx * AS1 + 128 + comp] = hi_h(vn);
            An[fsx * AS1 + 132 + comp] = lo_h(vn);
            vn = vi;
            vi = (t + 3 < TT) ? __ldg(xp + (size_t)(t + 3) * step * 4) : 0.f;
        }

        // epilogue (rows 0..7 only): items u=0,1
        {
            float iv = sigmoid_f(acc[0][0] + bi0);
            float fv = sigmoid_f(acc[0][1] + bff0);
            float gv = tanh_f   (acc[1][0] + bg0);
            float ov = sigmoid_f(acc[1][1] + bo0);
            c0 = fv * c0 + iv * gv;
            float hh = ov * tanh_f(c0);
            An[srow * AS1 + j0]      = hi_h(hh);
            An[srow * AS1 + 64 + j0] = lo_h(hh);

            iv = sigmoid_f(acc[2][0] + bi1);
            fv = sigmoid_f(acc[2][1] + bff1);
            gv = tanh_f   (acc[3][0] + bg1);
            ov = sigmoid_f(acc[3][1] + bo1);
            c1 = fv * c1 + iv * gv;
            hh = ov * tanh_f(c1);
            An[srow * AS1 + j1]      = hi_h(hh);
            An[srow * AS1 + 64 + j1] = lo_h(hh);
        }
        __syncthreads();
    }

    if (tid < 128) {
        uint2 v = *(const uint2*)(A + ffs * AS1 + ffc * 4);
        *(uint2*)(fout + (size_t)(t0 + (TT - 1) * step) * 128) = v;
    }
}

// =====================================================================
// pre2 GEMM: g_pre2p[m, n2] = sum_k out1h[m,k] * B2i[n2,k] + b2[r2(n2)]
// M = B*T, K = 128, N = 256, output permuted + bias folded.
// =====================================================================
#define ASG 136
__global__ __launch_bounds__(256, 2)
void pre2_gemm(const float* __restrict__ b2)
{
    const int m0 = blockIdx.x * 128;
    const int tid = threadIdx.x, lane = tid & 31, w = tid >> 5;

    __shared__ __half As[128 * ASG];

    {
        const uint4* src = (const uint4*)(g_out1h + (size_t)m0 * 128);
        for (int i = tid; i < 128 * 16; i += 256) {
            int rr = i >> 4, cc = i & 15;
            *(uint4*)&As[rr * ASG + cc * 8] = __ldg(src + i);
        }
    }
    __syncthreads();

    const uint32_t aaddr = smem_u32(As) + (((w * 16) + (lane & 15)) * ASG + (lane >> 4) * 8) * 2;

    float* outp = g_pre2p + (size_t)(m0 + w * 16) * 256;
    const int row0 = lane >> 2;

#pragma unroll 1
    for (int ng = 0; ng < 8; ng++) {
        uint32_t bfr[4][8][2];
#pragma unroll
        for (int tt = 0; tt < 4; tt++) {
            const int n = ng * 32 + tt * 8 + (lane >> 2);
#pragma unroll
            for (int kt = 0; kt < 8; kt++) {
                const __half* p = g_B2i + (size_t)n * 128 + kt * 16 + 2 * (lane & 3);
                bfr[tt][kt][0] = *(const uint32_t*)p;
                bfr[tt][kt][1] = *(const uint32_t*)(p + 8);
            }
        }

        float acc[4][4];
#pragma unroll
        for (int i = 0; i < 4; i++) { acc[i][0] = 0.f; acc[i][1] = 0.f; acc[i][2] = 0.f; acc[i][3] = 0.f; }
#pragma unroll
        for (int kt = 0; kt < 8; kt++) {
            uint32_t a[4];
            ldsm4(a, aaddr + kt * 32);
            mma16816(acc[0], a, bfr[0][kt]);
            mma16816(acc[1], a, bfr[1][kt]);
            mma16816(acc[2], a, bfr[2][kt]);
            mma16816(acc[3], a, bfr[3][kt]);
        }

#pragma unroll
        for (int tt = 0; tt < 4; tt++) {
            const int col = ng * 32 + tt * 8 + 2 * (lane & 3);
            const int ra = (col & 3) * 64 + (col >> 2);
            const int rb = ((col + 1) & 3) * 64 + ((col + 1) >> 2);
            const float ba = __ldg(b2 + ra), bb = __ldg(b2 + rb);
            float2 v0 = make_float2(acc[tt][0] + ba, acc[tt][1] + bb);
            float2 v1 = make_float2(acc[tt][2] + ba, acc[tt][3] + bb);
            *(float2*)(outp + (size_t)row0 * 256 + col)       = v0;
            *(float2*)(outp + (size_t)(row0 + 8) * 256 + col) = v1;
        }
    }
}

// =====================================================================
// Layer-2 scan: 8 samples/block, 32 blocks. K=128 (h hi/lo only).
// pre2 preactivations streamed per-lane as float4. Fused FC.
// =====================================================================
#define AS2 136
__global__ __launch_bounds__(256, 1)
void l2_scan(const float* __restrict__ Wfc, const float* __restrict__ bfc,
             float* __restrict__ out)
{
    const int s0  = blockIdx.x * 8;
    const int tid = threadIdx.x, lane = tid & 31, w = tid >> 5;

    __shared__ __half A[2 * 16 * AS2];
    __shared__ float  sred[8 * 64];

    for (int i = tid; i < 2 * 16 * AS2; i += 256) A[i] = __ushort_as_half(0);

    uint32_t bf[4][8][2];
#pragma unroll
    for (int tt = 0; tt < 4; tt++) {
        const int n = (w * 4 + tt) * 8 + (lane >> 2);
#pragma unroll
        for (int kt = 0; kt < 8; kt++) {
            const __half* p = g_B2s + (size_t)n * 128 + kt * 16 + 2 * (lane & 3);
            bf[tt][kt][0] = *(const uint32_t*)p;
            bf[tt][kt][1] = *(const uint32_t*)(p + 8);
        }
    }

    const int j0 = w * 8 + (lane & 3), j1 = j0 + 4;
    const float wf0 = __ldg(Wfc + j0), wf1 = __ldg(Wfc + j1);

    const uint32_t lrow = lane & 15, lcol = (lane >> 4) * 8;
    const uint32_t aaddr0 = smem_u32(A) + (lrow * AS2 + lcol) * 2;
    const uint32_t aaddr1 = aaddr0 + 16 * AS2 * 2;

    const int srow = lane >> 2;

    // pre2 stream: lane reads float4 quads (i,f,g,o) for items u=0,1
    const float* pp = g_pre2p + (size_t)(s0 + srow) * TT * 256 + w * 32 + (lane & 3) * 4;
    float4 pc0 = *(const float4*)(pp);
    float4 pc1 = *(const float4*)(pp + 16);
    float4 pn0 = *(const float4*)(pp + 256);
    float4 pn1 = *(const float4*)(pp + 256 + 16);
    __syncthreads();

    float c0 = 0.f, c1 = 0.f;
    float h0 = 0.f, h1 = 0.f;

    for (int t = 0; t < TT; t++) {
        const int cur = t & 1, nxt = cur ^ 1;
        const uint32_t aaddr = cur ? aaddr1 : aaddr0;
        __half* An = A + nxt * 16 * AS2;

        float acc[4][4];
#pragma unroll
        for (int i = 0; i < 4; i++) { acc[i][0] = 0.f; acc[i][1] = 0.f; acc[i][2] = 0.f; acc[i][3] = 0.f; }
#pragma unroll
        for (int kt = 0; kt < 8; kt++) {
            uint32_t a[4];
            ldsm4(a, aaddr + kt * 32);
            mma16816(acc[0], a, bf[0][kt]);
            mma16816(acc[1], a, bf[1][kt]);
            mma16816(acc[2], a, bf[2][kt]);
            mma16816(acc[3], a, bf[3][kt]);
        }

        float4 pf0, pf1;
        if (t + 2 < TT) {
            pf0 = *(const float4*)(pp + (size_t)(t + 2) * 256);
            pf1 = *(const float4*)(pp + (size_t)(t + 2) * 256 + 16);
        } else { pf0 = make_float4(0.f,0.f,0.f,0.f); pf1 = pf0; }

        {
            float iv = sigmoid_f(acc[0][0] + pc0.x);
            float fv = sigmoid_f(acc[0][1] + pc0.y);
            float gv = tanh_f   (acc[1][0] + pc0.z);
            float ov = sigmoid_f(acc[1][1] + pc0.w);
            c0 = fv * c0 + iv * gv;
            h0 = ov * tanh_f(c0);
            An[srow * AS2 + j0]      = hi_h(h0);
            An[srow * AS2 + 64 + j0] = lo_h(h0);

            iv = sigmoid_f(acc[2][0] + pc1.x);
            fv = sigmoid_f(acc[2][1] + pc1.y);
            gv = tanh_f   (acc[3][0] + pc1.z);
            ov = sigmoid_f(acc[3][1] + pc1.w);
            c1 = fv * c1 + iv * gv;
            h1 = ov * tanh_f(c1);
            An[srow * AS2 + j1]      = hi_h(h1);
            An[srow * AS2 + 64 + j1] = lo_h(h1);
        }

        pc0 = pn0; pc1 = pn1; pn0 = pf0; pn1 = pf1;
        __syncthreads();
    }

    sred[srow * 64 + j0] = h0 * wf0;
    sred[srow * 64 + j1] = h1 * wf1;
    __syncthreads();
    if (tid < 8) {
        float acc = __ldg(bfc);
#pragma unroll
        for (int k = 0; k < 64; k++) acc += sred[tid * 64 + k];
        out[s0 + tid] = acc;
    }
}

// =====================================================================
extern "C" void kernel_launch(void* const* d_in, const int* in_sizes, int n_in,
                              void* d_out, int out_size)
{
    const float* x     = (const float*)d_in[0];
    const float* Wih_f = (const float*)d_in[1];
    const float* Whh_f = (const float*)d_in[2];
    const float* b_f   = (const float*)d_in[3];
    const float* Wih_b = (const float*)d_in[4];
    const float* Whh_b = (const float*)d_in[5];
    const float* b_b   = (const float*)d_in[6];
    const float* Wih2  = (const float*)d_in[7];
    const float* Whh2  = (const float*)d_in[8];
    const float* b2    = (const float*)d_in[9];
    const float* Wfc   = (const float*)d_in[10];
    const float* bfc   = (const float*)d_in[11];
    float* out = (float*)d_out;

    build_B<<<256, 256>>>(Wih_f, Whh_f, Wih_b, Whh_b, Wih2, Whh2);
    l1_scan<<<64, 256>>>(x, b_f, b_b);
    pre2_gemm<<<(BB * TT) / 128, 256>>>(b2);
    l2_scan<<<32, 256>>>(Wfc, bfc, out);
}